// round 8
// baseline (speedup 1.0000x reference)
#include <cuda_runtime.h>
#include <cstdint>

// Fixed shapes
#define TT    16
#define HH    1280
#define WW    1280
#define NB    64
#define W4    (WW / 4)           // 320 float4 per row
#define HW4   (HH * W4)          // 409,600 float4 per frame
#define NTHR  W4                 // 320 threads: one float4 (4 cols) per thread
#define NBLK  HH                 // one block per row
#define NWARP (NTHR / 32)        // 10 warps
#define NSLOT 32                 // spread accumulator (kills per-address atomic serialization)

__device__ double       g_slots[NSLOT];   // zero-initialized at module load; reset each replay
__device__ unsigned int g_count = 0u;

// ---------------------------------------------------------------------------
// One block per row y:
//   0) boxes LDG issued FIRST (off the barrier critical path), then prefetch
//      8 frames with L1-bypassing __ldcg (pure streaming, no reuse)
//   1) row weights via shared difference array + block prefix scan
//   2) remaining 8 frames in 2 batches of 4
//   3) warp+block reduce -> atomicAdd(double) to 1 of 32 slots
//   4) last block folds slots, writes scalar, resets state for next replay
// ---------------------------------------------------------------------------
__global__ void __launch_bounds__(NTHR, 4) fused_kernel(const float* __restrict__ data,
                                                        const int*   __restrict__ boxes,
                                                        float* __restrict__ out) {
    __shared__ int   sdiff[WW];
    __shared__ int   wsum[NWARP];
    __shared__ float warp_sums[NWARP];

    const int tid  = threadIdx.x;        // 0..319
    const int y    = blockIdx.x;         // row
    const int lane = tid & 31;
    const int wid  = tid >> 5;

    // ---- boxes load first: in flight before anything else ----
    int4 b = make_int4(0, 0, 0, 0);
    if (tid < NB) b = __ldg(reinterpret_cast<const int4*>(boxes) + tid); // x1,y1,x2,y2

    // ---- prefetch 8 frames, L2-only (no L1 pollution) ----
    const float4* p = reinterpret_cast<const float4*>(data) + (size_t)y * W4 + tid;
    float4 v0 = __ldcg(p + 0 * (size_t)HW4);
    float4 v1 = __ldcg(p + 1 * (size_t)HW4);
    float4 v2 = __ldcg(p + 2 * (size_t)HW4);
    float4 v3 = __ldcg(p + 3 * (size_t)HW4);
    float4 v4 = __ldcg(p + 4 * (size_t)HW4);
    float4 v5 = __ldcg(p + 5 * (size_t)HW4);
    float4 v6 = __ldcg(p + 6 * (size_t)HW4);
    float4 v7 = __ldcg(p + 7 * (size_t)HW4);

    // ---- weights: difference array + block scan ----
    reinterpret_cast<int4*>(sdiff)[tid] = make_int4(0, 0, 0, 0);
    __syncthreads();

    if (tid < NB && b.y <= y && y < b.w) {
        atomicAdd(&sdiff[b.x],  1);
        atomicAdd(&sdiff[b.z], -1);          // x2 <= 1279 < WW
    }
    __syncthreads();

    int4 c = reinterpret_cast<const int4*>(sdiff)[tid];
    int s0 = c.x, s1 = s0 + c.y, s2 = s1 + c.z, s3 = s2 + c.w;
    const int tot = s3;

    int v = tot;
#pragma unroll
    for (int off = 1; off < 32; off <<= 1) {
        int n = __shfl_up_sync(0xFFFFFFFFu, v, off);
        if (lane >= off) v += n;
    }
    if (lane == 31) wsum[wid] = v;
    __syncthreads();

    int wprefix = 0;
#pragma unroll
    for (int i = 0; i < NWARP; i++)
        if (i < wid) wprefix += wsum[i];
    const int base = wprefix + (v - tot);    // exclusive prefix before this thread

    const float w0 = (float)(base + s0);
    const float w1 = (float)(base + s1);
    const float w2 = (float)(base + s2);
    const float w3 = (float)(base + s3);

    // ---- fold prefetched frames (two banks for ILP) ----
    float a0 = (v0.x + v1.x) + (v2.x + v3.x);
    float a1 = (v0.y + v1.y) + (v2.y + v3.y);
    float a2 = (v0.z + v1.z) + (v2.z + v3.z);
    float a3 = (v0.w + v1.w) + (v2.w + v3.w);
    float b0 = (v4.x + v5.x) + (v6.x + v7.x);
    float b1 = (v4.y + v5.y) + (v6.y + v7.y);
    float b2 = (v4.z + v5.z) + (v6.z + v7.z);
    float b3 = (v4.w + v5.w) + (v6.w + v7.w);

    // ---- remaining 8 frames: 2 batches of 4 independent loads ----
#pragma unroll
    for (int t = 8; t < TT; t += 4) {
        float4 q0 = __ldcg(p + (size_t)(t + 0) * HW4);
        float4 q1 = __ldcg(p + (size_t)(t + 1) * HW4);
        float4 q2 = __ldcg(p + (size_t)(t + 2) * HW4);
        float4 q3 = __ldcg(p + (size_t)(t + 3) * HW4);
        a0 += (q0.x + q1.x) + (q2.x + q3.x);
        a1 += (q0.y + q1.y) + (q2.y + q3.y);
        a2 += (q0.z + q1.z) + (q2.z + q3.z);
        a3 += (q0.w + q1.w) + (q2.w + q3.w);
    }

    float s = fmaf(w0, a0 + b0, fmaf(w1, a1 + b1, fmaf(w2, a2 + b2, w3 * (a3 + b3))));

    // ---- warp reduce ----
#pragma unroll
    for (int off = 16; off > 0; off >>= 1)
        s += __shfl_down_sync(0xFFFFFFFFu, s, off);
    if (lane == 0) warp_sums[wid] = s;
    __syncthreads();

    if (tid == 0) {
        float bsum = warp_sums[0];
#pragma unroll
        for (int i = 1; i < NWARP; i++) bsum += warp_sums[i];

        atomicAdd(&g_slots[y & (NSLOT - 1)], (double)bsum);
        __threadfence();
        unsigned old = atomicAdd(&g_count, 1u);
        if (old == NBLK - 1u) {
            __threadfence();
            double total = 0.0;
            volatile double* vs = g_slots;
#pragma unroll
            for (int i = 0; i < NSLOT; i++) {
                total += vs[i];
                vs[i] = 0.0;                 // reset for next graph replay
            }
            out[0] = (float)total;
            __threadfence();
            g_count = 0u;
        }
    }
}

extern "C" void kernel_launch(void* const* d_in, const int* in_sizes, int n_in,
                              void* d_out, int out_size) {
    const float* data  = (const float*)d_in[0];  // (16,1280,1280) fp32
    const int*   boxes = (const int*)d_in[1];    // (64,4) int32 [x1,y1,x2,y2]
    float*       out   = (float*)d_out;

    fused_kernel<<<NBLK, NTHR>>>(data, boxes, out);
}